// round 2
// baseline (speedup 1.0000x reference)
#include <cuda_runtime.h>
#include <cuda_bf16.h>
#include <stdint.h>

#define NPTS 200000
#define DIM 64
#define KC 256
#define BW2 144.0f
#define TK 64
#define TN 64
#define NTILES 3125      // NPTS / TN
#define GX 111           // point-dimension blocks (444 total = 148 SM * 3)
#define ITERS 10

__device__ float g_c[2][KC][DIM];
__device__ float g_acc[KC][DIM];
__device__ float g_cnt[KC];
__device__ float g_x2[NPTS];
__device__ unsigned long long g_best[KC];
__device__ int g_seed64;

// ---------------------------------------------------------------- utilities

__global__ void x2_kernel(const float* __restrict__ x) {
    int n = blockIdx.x * blockDim.x + threadIdx.x;
    if (n >= NPTS) return;
    const float4* r = (const float4*)(x + (size_t)n * DIM);
    float s = 0.f;
#pragma unroll
    for (int i = 0; i < DIM / 4; i++) {
        float4 v = r[i];
        s = fmaf(v.x, v.x, s); s = fmaf(v.y, v.y, s);
        s = fmaf(v.z, v.z, s); s = fmaf(v.w, v.w, s);
    }
    g_x2[n] = s;
}

// Probe whether the seed buffer is int64 (reference dtype) or int32.
// Reading 128 u64 = 1024B is safe under both interpretations (256 i32 = 1KB).
__global__ void detect_kernel(const void* __restrict__ seed) {
    __shared__ int bad;
    if (threadIdx.x == 0) bad = 0;
    __syncthreads();
    const unsigned long long* s64 = (const unsigned long long*)seed;
    unsigned long long v = s64[threadIdx.x];
    if (v >= (unsigned long long)NPTS) atomicOr(&bad, 1);
    __syncthreads();
    if (threadIdx.x == 0) g_seed64 = bad ? 0 : 1;
}

__global__ void seed_kernel(const float* __restrict__ x, const void* __restrict__ seedraw) {
    int k = blockIdx.x, d = threadIdx.x;
    long long idx;
    if (g_seed64) idx = ((const long long*)seedraw)[k];
    else          idx = (long long)(((const int*)seedraw)[k]);
    g_c[0][k][d] = x[idx * DIM + d];
    g_acc[k][d] = 0.f;
    if (d == 0) { g_cnt[k] = 0.f; g_best[k] = ~0ull; }
}

__global__ void update_kernel(int it) {
    int k = blockIdx.x, d = threadIdx.x;
    float cnt = g_cnt[k];
    float v = g_acc[k][d] / cnt;
    __syncthreads();
    g_c[(it + 1) & 1][k][d] = v;
    g_acc[k][d] = 0.f;
    if (d == 0) g_cnt[k] = 0.f;
}

// ------------------------------------------- fused mask + accumulate GEMMs
// Block tile: 64 centers x 64 points, 256 threads, 4x4 register micro-tiles.
// Phase 1: S = C . X^T from Cs[d][ck] / Xt[d][p] (both float4 along
//          thread-varying index; center operand is warp-broadcast -> smem-cheap).
// Phase 2: acc[ck][d] += M[p][ck] * X[p][d] from Ms[p][ck] / Xr[p][d].

__global__ void __launch_bounds__(256) iter_kernel(const float* __restrict__ x, int it) {
    extern __shared__ float smem[];
    float* Cs  = smem;                 // [64][64]  centers, transposed
    float* c2s = Cs + 64 * 64;         // [64]
    float* Xt  = c2s + 64;             // [64][68]  x tile, transposed (padded)
    float* Xr  = Xt + 64 * 68;         // [64][68]  x tile, row-major (padded)
    float* Ms  = Xr + 64 * 68;         // [64][68]  mask tile [p][ck] (padded)
    float* x2s = Ms + 64 * 68;         // [64]

    const int tid = threadIdx.x;
    const int kb  = blockIdx.y * TK;
    const float* cin = &g_c[it & 1][0][0];

    { // centers -> Cs transposed
        int ck = tid >> 2, q = tid & 3;
        const float4* row = (const float4*)(cin + (size_t)(kb + ck) * DIM + q * 16);
#pragma unroll
        for (int i = 0; i < 4; i++) {
            float4 v = row[i];
            int dd = q * 16 + i * 4;
            Cs[(dd + 0) * TK + ck] = v.x;
            Cs[(dd + 1) * TK + ck] = v.y;
            Cs[(dd + 2) * TK + ck] = v.z;
            Cs[(dd + 3) * TK + ck] = v.w;
        }
    }
    __syncthreads();
    if (tid < TK) {
        float s = 0.f;
#pragma unroll
        for (int d = 0; d < DIM; d++) { float c = Cs[d * TK + tid]; s = fmaf(c, c, s); }
        c2s[tid] = s;
    }

    const int ty = tid >> 4, tx = tid & 15;
    const int ck0 = ty * 4, p0 = tx * 4, dq = tx * 4;

    float acc2[4][4] = {};
    float cnt4[4] = {0.f, 0.f, 0.f, 0.f};

    for (int t = blockIdx.x; t < NTILES; t += GX) {
        const int tb = t * TN;
        __syncthreads();             // prev phase2 done with Xr/Ms; covers c2s on 1st pass
        {                            // load x tile -> Xr (direct) + Xt (transposed)
            int p = tid >> 2, q = tid & 3;
            const float4* row = (const float4*)(x + (size_t)(tb + p) * DIM + q * 16);
#pragma unroll
            for (int i = 0; i < 4; i++) {
                float4 v = row[i];
                int dd = q * 16 + i * 4;
                *(float4*)(Xr + p * 68 + dd) = v;
                Xt[(dd + 0) * 68 + p] = v.x;
                Xt[(dd + 1) * 68 + p] = v.y;
                Xt[(dd + 2) * 68 + p] = v.z;
                Xt[(dd + 3) * 68 + p] = v.w;
            }
            if (tid < TN) x2s[tid] = g_x2[tb + tid];
        }
        __syncthreads();

        // phase 1: dots
        float S[4][4] = {};
#pragma unroll 4
        for (int dd = 0; dd < DIM; dd++) {
            float4 cv4 = *(const float4*)(Cs + dd * TK + ck0);
            float4 xv4 = *(const float4*)(Xt + dd * 68 + p0);
            float cv[4] = {cv4.x, cv4.y, cv4.z, cv4.w};
            float xv[4] = {xv4.x, xv4.y, xv4.z, xv4.w};
#pragma unroll
            for (int i = 0; i < 4; i++)
#pragma unroll
                for (int j = 0; j < 4; j++)
                    S[i][j] = fmaf(cv[i], xv[j], S[i][j]);
        }
        // mask -> Ms (and per-thread partial counts)
#pragma unroll
        for (int j = 0; j < 4; j++) {
            float xv2 = x2s[p0 + j];
            float4 mv;
            mv.x = (fmaf(-2.f, S[0][j], c2s[ck0 + 0] + xv2) < BW2) ? 1.f : 0.f;
            mv.y = (fmaf(-2.f, S[1][j], c2s[ck0 + 1] + xv2) < BW2) ? 1.f : 0.f;
            mv.z = (fmaf(-2.f, S[2][j], c2s[ck0 + 2] + xv2) < BW2) ? 1.f : 0.f;
            mv.w = (fmaf(-2.f, S[3][j], c2s[ck0 + 3] + xv2) < BW2) ? 1.f : 0.f;
            cnt4[0] += mv.x; cnt4[1] += mv.y; cnt4[2] += mv.z; cnt4[3] += mv.w;
            *(float4*)(Ms + (p0 + j) * 68 + ck0) = mv;
        }
        __syncthreads();

        // phase 2: acc[ck][d] += M[p][ck] * X[p][d]
#pragma unroll 4
        for (int p = 0; p < TN; p++) {
            float4 mv4 = *(const float4*)(Ms + p * 68 + ck0);
            float4 xv4 = *(const float4*)(Xr + p * 68 + dq);
            float mv[4] = {mv4.x, mv4.y, mv4.z, mv4.w};
            float xv[4] = {xv4.x, xv4.y, xv4.z, xv4.w};
#pragma unroll
            for (int i = 0; i < 4; i++)
#pragma unroll
                for (int j = 0; j < 4; j++)
                    acc2[i][j] = fmaf(mv[i], xv[j], acc2[i][j]);
        }
    }

#pragma unroll
    for (int i = 0; i < 4; i++)
#pragma unroll
        for (int j = 0; j < 4; j++)
            atomicAdd(&g_acc[kb + ck0 + i][dq + j], acc2[i][j]);

#pragma unroll
    for (int i = 0; i < 4; i++) {
        float v = cnt4[i];
#pragma unroll
        for (int off = 8; off > 0; off >>= 1)
            v += __shfl_down_sync(0xffffffffu, v, off, 16);
        if (tx == 0) atomicAdd(&g_cnt[kb + ck0 + i], v);
    }
}

// ------------------------------------------- final masked argmin pass
// mask uses centers after 9 updates (g_c[1]); distance uses centers after 10
// updates (g_c[0]). Key = (d2_bits << 32) | index  -> atomicMin reproduces
// argmin semantics (min distance, first index on ties).

__global__ void __launch_bounds__(256) final_kernel(const float* __restrict__ x) {
    extern __shared__ float smem[];
    float* C9   = smem;                // [64][64]
    float* C10  = C9 + 64 * 64;        // [64][64]
    float* c29  = C10 + 64 * 64;       // [64]
    float* c210 = c29 + 64;            // [64]
    float* Xt   = c210 + 64;           // [64][68]
    float* x2s  = Xt + 64 * 68;        // [64]

    const int tid = threadIdx.x;
    const int kb  = blockIdx.y * TK;

    {
        int ck = tid >> 2, q = tid & 3;
        const float4* r9  = (const float4*)(&g_c[1][kb + ck][0] + q * 16);
        const float4* r10 = (const float4*)(&g_c[0][kb + ck][0] + q * 16);
#pragma unroll
        for (int i = 0; i < 4; i++) {
            float4 a = r9[i], b = r10[i];
            int dd = q * 16 + i * 4;
            C9[(dd + 0) * TK + ck] = a.x; C9[(dd + 1) * TK + ck] = a.y;
            C9[(dd + 2) * TK + ck] = a.z; C9[(dd + 3) * TK + ck] = a.w;
            C10[(dd + 0) * TK + ck] = b.x; C10[(dd + 1) * TK + ck] = b.y;
            C10[(dd + 2) * TK + ck] = b.z; C10[(dd + 3) * TK + ck] = b.w;
        }
    }
    __syncthreads();
    if (tid < TK) {
        float s9 = 0.f, s10 = 0.f;
#pragma unroll
        for (int d = 0; d < DIM; d++) {
            float a = C9[d * TK + tid];  s9  = fmaf(a, a, s9);
            float b = C10[d * TK + tid]; s10 = fmaf(b, b, s10);
        }
        c29[tid] = s9; c210[tid] = s10;
    }

    const int ty = tid >> 4, tx = tid & 15;
    const int ck0 = ty * 4, p0 = tx * 4;
    unsigned long long best[4] = {~0ull, ~0ull, ~0ull, ~0ull};

    for (int t = blockIdx.x; t < NTILES; t += GX) {
        const int tb = t * TN;
        __syncthreads();
        {
            int p = tid >> 2, q = tid & 3;
            const float4* row = (const float4*)(x + (size_t)(tb + p) * DIM + q * 16);
#pragma unroll
            for (int i = 0; i < 4; i++) {
                float4 v = row[i];
                int dd = q * 16 + i * 4;
                Xt[(dd + 0) * 68 + p] = v.x;
                Xt[(dd + 1) * 68 + p] = v.y;
                Xt[(dd + 2) * 68 + p] = v.z;
                Xt[(dd + 3) * 68 + p] = v.w;
            }
            if (tid < TN) x2s[tid] = g_x2[tb + tid];
        }
        __syncthreads();

        float S9[4][4] = {}, S10[4][4] = {};
#pragma unroll 2
        for (int dd = 0; dd < DIM; dd++) {
            float4 c9v = *(const float4*)(C9 + dd * TK + ck0);
            float4 cav = *(const float4*)(C10 + dd * TK + ck0);
            float4 xv4 = *(const float4*)(Xt + dd * 68 + p0);
            float a9[4] = {c9v.x, c9v.y, c9v.z, c9v.w};
            float aa[4] = {cav.x, cav.y, cav.z, cav.w};
            float xv[4] = {xv4.x, xv4.y, xv4.z, xv4.w};
#pragma unroll
            for (int i = 0; i < 4; i++)
#pragma unroll
                for (int j = 0; j < 4; j++) {
                    S9[i][j]  = fmaf(a9[i], xv[j], S9[i][j]);
                    S10[i][j] = fmaf(aa[i], xv[j], S10[i][j]);
                }
        }
#pragma unroll
        for (int j = 0; j < 4; j++) {
            float xv2 = x2s[p0 + j];
            unsigned idx = (unsigned)(tb + p0 + j);
#pragma unroll
            for (int i = 0; i < 4; i++) {
                float d2m = fmaf(-2.f, S9[i][j], c29[ck0 + i] + xv2);
                if (d2m < BW2) {
                    float d2 = fmaf(-2.f, S10[i][j], c210[ck0 + i] + xv2);
                    d2 = fmaxf(d2, 0.f);
                    unsigned long long key =
                        ((unsigned long long)__float_as_uint(d2) << 32) | idx;
                    if (key < best[i]) best[i] = key;
                }
            }
        }
    }

#pragma unroll
    for (int i = 0; i < 4; i++) {
        unsigned long long v = best[i];
#pragma unroll
        for (int off = 8; off > 0; off >>= 1) {
            unsigned long long o = __shfl_down_sync(0xffffffffu, v, off, 16);
            if (o < v) v = o;
        }
        if (tx == 0) atomicMin(&g_best[kb + ck0 + i], v);
    }
}

// ---------------------------------------------------------------- epilogue

__global__ void zero_out(float* out, int n) {
    int i = blockIdx.x * blockDim.x + threadIdx.x;
    if (i < n) out[i] = 0.f;
}

__global__ void finish_kernel(float* __restrict__ out, const float* __restrict__ x,
                              int out_size) {
    int k = blockIdx.x, d = threadIdx.x;
    if (out_size >= KC * DIM)
        out[k * DIM + d] = g_c[0][k][d];
    unsigned long long b = g_best[k];
    unsigned idx = (b == ~0ull) ? 0u : (unsigned)(b & 0xffffffffu);
    if (out_size >= 2 * KC * DIM)
        out[KC * DIM + k * DIM + d] = x[(size_t)idx * DIM + d];
    if (d == 0 && out_size >= 2 * KC * DIM + KC)
        out[2 * KC * DIM + k] = (float)idx;
}

// ---------------------------------------------------------------- launcher

extern "C" void kernel_launch(void* const* d_in, const int* in_sizes, int n_in,
                              void* d_out, int out_size) {
    const float* x = (const float*)d_in[0];
    const void* seed = d_in[1];
    float* out = (float*)d_out;
    (void)in_sizes; (void)n_in;

    const size_t iterSmem  = (size_t)(64 * 64 + 64 + 3 * 64 * 68 + 64) * sizeof(float);
    const size_t finalSmem = (size_t)(2 * 64 * 64 + 2 * 64 + 64 * 68 + 64) * sizeof(float);
    cudaFuncSetAttribute(iter_kernel,  cudaFuncAttributeMaxDynamicSharedMemorySize, (int)iterSmem);
    cudaFuncSetAttribute(final_kernel, cudaFuncAttributeMaxDynamicSharedMemorySize, (int)finalSmem);

    x2_kernel<<<(NPTS + 255) / 256, 256>>>(x);
    detect_kernel<<<1, 128>>>(seed);
    seed_kernel<<<KC, DIM>>>(x, seed);

    for (int it = 0; it < ITERS; it++) {
        iter_kernel<<<dim3(GX, KC / TK), 256, iterSmem>>>(x, it);
        update_kernel<<<KC, DIM>>>(it);
    }

    final_kernel<<<dim3(GX, KC / TK), 256, finalSmem>>>(x);

    if (out_size > 0)
        zero_out<<<(out_size + 255) / 256, 256>>>(out, out_size);
    finish_kernel<<<KC, DIM>>>(out, x, out_size);
}

// round 3
// speedup vs baseline: 1.2470x; 1.2470x over previous
#include <cuda_runtime.h>
#include <cuda_bf16.h>
#include <stdint.h>

#define NPTS 200000
#define DIM 64
#define KC 256
#define BW2 144.0f
#define ITERS 10

#define KB 128
#define PB 128
#define NT128 1563
#define GXI 74
#define XTS 132
#define XRS 68
#define MSS 132

#define TK 64
#define TN 64
#define NT64 3125
#define GXF 111

typedef unsigned long long u64p;
#define PK2(d, lo, hi) asm("mov.b64 %0, {%1, %2};" : "=l"(d) : "f"(lo), "f"(hi))
#define UPK2(lo, hi, s) asm("mov.b64 {%0, %1}, %2;" : "=f"(lo), "=f"(hi) : "l"(s))
#define FMA2(d, a, b, c) asm("fma.rn.f32x2 %0, %1, %2, %3;" : "=l"(d) : "l"(a), "l"(b), "l"(c))
#define ADD2(d, a, b) asm("add.rn.f32x2 %0, %1, %2;" : "=l"(d) : "l"(a), "l"(b))

__device__ float g_c[2][KC][DIM];
__device__ float g_acc[KC][DIM];
__device__ float g_cnt[KC];
__device__ float g_x2[NPTS];
__device__ unsigned long long g_best[KC];
__device__ int g_seed64;

__global__ void x2_kernel(const float* __restrict__ x) {
    int n = blockIdx.x * blockDim.x + threadIdx.x;
    if (n >= NPTS) return;
    const float4* r = (const float4*)(x + (size_t)n * DIM);
    float s = 0.f;
#pragma unroll
    for (int i = 0; i < DIM / 4; i++) {
        float4 v = r[i];
        s = fmaf(v.x, v.x, s); s = fmaf(v.y, v.y, s);
        s = fmaf(v.z, v.z, s); s = fmaf(v.w, v.w, s);
    }
    g_x2[n] = s;
}

__global__ void detect_kernel(const void* __restrict__ seed) {
    __shared__ int bad;
    if (threadIdx.x == 0) bad = 0;
    __syncthreads();
    unsigned long long v = ((const unsigned long long*)seed)[threadIdx.x];
    if (v >= (unsigned long long)NPTS) atomicOr(&bad, 1);
    __syncthreads();
    if (threadIdx.x == 0) g_seed64 = bad ? 0 : 1;
}

__global__ void seed_kernel(const float* __restrict__ x, const void* __restrict__ seedraw) {
    int k = blockIdx.x, d = threadIdx.x;
    long long idx;
    if (g_seed64) idx = ((const long long*)seedraw)[k];
    else          idx = (long long)(((const int*)seedraw)[k]);
    g_c[0][k][d] = x[idx * DIM + d];
    g_acc[k][d] = 0.f;
    if (d == 0) { g_cnt[k] = 0.f; g_best[k] = ~0ull; }
}

__global__ void update_kernel(int it) {
    int k = blockIdx.x, d = threadIdx.x;
    float cnt = g_cnt[k];
    float v = g_acc[k][d] / cnt;
    __syncthreads();
    g_c[(it + 1) & 1][k][d] = v;
    g_acc[k][d] = 0.f;
    if (d == 0) g_cnt[k] = 0.f;
}

// fused mask+accumulate GEMMs, 128x128 tile, f32x2 packed math
__global__ void __launch_bounds__(256, 1) iter_kernel(const float* __restrict__ x, int it) {
    extern __shared__ float smem[];
    float* Cs  = smem;              // [64][128]
    float* c2s = Cs + 64 * KB;      // [128]
    float* Xt  = c2s + KB;          // [64][132]
    float* Xr  = Xt + 64 * XTS;     // [128][68]
    float* Ms  = Xr + PB * XRS;     // [128][132] swizzled
    float* x2s = Ms + PB * MSS;     // [128]

    const int tid = threadIdx.x;
    const int ty = tid >> 4, tx = tid & 15;
    const int ck0 = ty * 8, p0 = tx * 8, dq = tx * 4;
    const int kb = blockIdx.y * KB;
    const float* cin = &g_c[it & 1][0][0];

    for (int e = tid; e < KB * DIM; e += 256) {
        int ck = e & (KB - 1), d = e >> 7;
        Cs[d * KB + ck] = cin[(size_t)(kb + ck) * DIM + d];
    }
    __syncthreads();
    if (tid < KB) {
        float s = 0.f;
#pragma unroll
        for (int d = 0; d < DIM; d++) { float c = Cs[d * KB + tid]; s = fmaf(c, c, s); }
        c2s[tid] = s;
    }
    __syncthreads();

    u64p c2d[8];
#pragma unroll
    for (int i = 0; i < 8; i++) { float v = c2s[ck0 + i]; PK2(c2d[i], v, v); }
    u64p neg2; { float m2 = -2.0f; PK2(neg2, m2, m2); }

    u64p acc2[4][4];
#pragma unroll
    for (int i = 0; i < 4; i++)
#pragma unroll
        for (int j = 0; j < 4; j++) acc2[i][j] = 0ull;
    float cnt[8] = {0.f, 0.f, 0.f, 0.f, 0.f, 0.f, 0.f, 0.f};

    for (int t = blockIdx.x; t < NT128; t += GXI) {
        const int tb = t * PB;
        __syncthreads();
        {
            int ploc = tid & 127, d0 = (tid >> 7) * 32;
            bool valid = (tb + ploc) < NPTS;
            const float4* src = (const float4*)(x + (size_t)(tb + ploc) * DIM + d0);
#pragma unroll
            for (int k = 0; k < 8; k++) {
                float4 v = valid ? src[k] : make_float4(0.f, 0.f, 0.f, 0.f);
                *(float4*)(Xr + ploc * XRS + d0 + 4 * k) = v;
                Xt[(d0 + 4 * k + 0) * XTS + ploc] = v.x;
                Xt[(d0 + 4 * k + 1) * XTS + ploc] = v.y;
                Xt[(d0 + 4 * k + 2) * XTS + ploc] = v.z;
                Xt[(d0 + 4 * k + 3) * XTS + ploc] = v.w;
            }
            if (tid < PB) x2s[tid] = ((tb + tid) < NPTS) ? g_x2[tb + tid] : 1e30f;
        }
        __syncthreads();

        // phase 1: dots (pairs along points)
        u64p S2[8][4];
#pragma unroll
        for (int i = 0; i < 8; i++)
#pragma unroll
            for (int j = 0; j < 4; j++) S2[i][j] = 0ull;

#pragma unroll 8
        for (int dd = 0; dd < DIM; dd++) {
            float4 ca = *(const float4*)(Cs + dd * KB + ck0);
            float4 cb = *(const float4*)(Cs + dd * KB + ck0 + 4);
            float4 xa = *(const float4*)(Xt + dd * XTS + p0);
            float4 xb = *(const float4*)(Xt + dd * XTS + p0 + 4);
            u64p xp[4];
            PK2(xp[0], xa.x, xa.y); PK2(xp[1], xa.z, xa.w);
            PK2(xp[2], xb.x, xb.y); PK2(xp[3], xb.z, xb.w);
            float cv[8] = {ca.x, ca.y, ca.z, ca.w, cb.x, cb.y, cb.z, cb.w};
#pragma unroll
            for (int i = 0; i < 8; i++) {
                u64p cd; PK2(cd, cv[i], cv[i]);
#pragma unroll
                for (int j = 0; j < 4; j++) FMA2(S2[i][j], cd, xp[j], S2[i][j]);
            }
        }

        // mask -> Ms (quad-XOR swizzle: phys group = logical group ^ (row>>3 & 7))
        {
            const int sw = tx & 7;
            const int colA = 4 * ((2 * ty) ^ sw);
            const int colB = 4 * ((2 * ty + 1) ^ sw);
#pragma unroll
            for (int jp = 0; jp < 4; jp++) {
                u64p x2p; PK2(x2p, x2s[p0 + 2 * jp], x2s[p0 + 2 * jp + 1]);
                float mlo[8], mhi[8];
#pragma unroll
                for (int i = 0; i < 8; i++) {
                    u64p tsum; ADD2(tsum, c2d[i], x2p);
                    u64p d2;   FMA2(d2, neg2, S2[i][jp], tsum);
                    float dlo, dhi; UPK2(dlo, dhi, d2);
                    mlo[i] = (dlo < BW2) ? 1.f : 0.f;
                    mhi[i] = (dhi < BW2) ? 1.f : 0.f;
                    cnt[i] += mlo[i] + mhi[i];
                }
                int pA = p0 + 2 * jp, pB = pA + 1;
                *(float4*)(Ms + pA * MSS + colA) = make_float4(mlo[0], mlo[1], mlo[2], mlo[3]);
                *(float4*)(Ms + pA * MSS + colB) = make_float4(mlo[4], mlo[5], mlo[6], mlo[7]);
                *(float4*)(Ms + pB * MSS + colA) = make_float4(mhi[0], mhi[1], mhi[2], mhi[3]);
                *(float4*)(Ms + pB * MSS + colB) = make_float4(mhi[4], mhi[5], mhi[6], mhi[7]);
            }
        }
        __syncthreads();

        // phase 2: acc += M^T X (pairs along centers)
#pragma unroll 4
        for (int p = 0; p < PB; p++) {
            const int sw = (p >> 3) & 7;
            float4 ma = *(const float4*)(Ms + p * MSS + 4 * ((2 * ty) ^ sw));
            float4 mb = *(const float4*)(Ms + p * MSS + 4 * ((2 * ty + 1) ^ sw));
            float4 xv = *(const float4*)(Xr + p * XRS + dq);
            u64p mp[4];
            PK2(mp[0], ma.x, ma.y); PK2(mp[1], ma.z, ma.w);
            PK2(mp[2], mb.x, mb.y); PK2(mp[3], mb.z, mb.w);
            u64p xd[4];
            PK2(xd[0], xv.x, xv.x); PK2(xd[1], xv.y, xv.y);
            PK2(xd[2], xv.z, xv.z); PK2(xd[3], xv.w, xv.w);
#pragma unroll
            for (int i2 = 0; i2 < 4; i2++)
#pragma unroll
                for (int j = 0; j < 4; j++) FMA2(acc2[i2][j], mp[i2], xd[j], acc2[i2][j]);
        }
    }

#pragma unroll
    for (int i2 = 0; i2 < 4; i2++)
#pragma unroll
        for (int j = 0; j < 4; j++) {
            float alo, ahi; UPK2(alo, ahi, acc2[i2][j]);
            atomicAdd(&g_acc[kb + ck0 + 2 * i2 + 0][dq + j], alo);
            atomicAdd(&g_acc[kb + ck0 + 2 * i2 + 1][dq + j], ahi);
        }
#pragma unroll
    for (int i = 0; i < 8; i++) {
        float v = cnt[i];
#pragma unroll
        for (int off = 8; off > 0; off >>= 1)
            v += __shfl_down_sync(0xffffffffu, v, off, 16);
        if (tx == 0) atomicAdd(&g_cnt[kb + ck0 + i], v);
    }
}

// final masked argmin (unchanged, known correct)
__global__ void __launch_bounds__(256) final_kernel(const float* __restrict__ x) {
    extern __shared__ float smem[];
    float* C9   = smem;
    float* C10  = C9 + 64 * 64;
    float* c29  = C10 + 64 * 64;
    float* c210 = c29 + 64;
    float* Xt   = c210 + 64;
    float* x2s  = Xt + 64 * 68;

    const int tid = threadIdx.x;
    const int kb  = blockIdx.y * TK;

    {
        int ck = tid >> 2, q = tid & 3;
        const float4* r9  = (const float4*)(&g_c[1][kb + ck][0] + q * 16);
        const float4* r10 = (const float4*)(&g_c[0][kb + ck][0] + q * 16);
#pragma unroll
        for (int i = 0; i < 4; i++) {
            float4 a = r9[i], b = r10[i];
            int dd = q * 16 + i * 4;
            C9[(dd + 0) * TK + ck] = a.x; C9[(dd + 1) * TK + ck] = a.y;
            C9[(dd + 2) * TK + ck] = a.z; C9[(dd + 3) * TK + ck] = a.w;
            C10[(dd + 0) * TK + ck] = b.x; C10[(dd + 1) * TK + ck] = b.y;
            C10[(dd + 2) * TK + ck] = b.z; C10[(dd + 3) * TK + ck] = b.w;
        }
    }
    __syncthreads();
    if (tid < TK) {
        float s9 = 0.f, s10 = 0.f;
#pragma unroll
        for (int d = 0; d < DIM; d++) {
            float a = C9[d * TK + tid];  s9  = fmaf(a, a, s9);
            float b = C10[d * TK + tid]; s10 = fmaf(b, b, s10);
        }
        c29[tid] = s9; c210[tid] = s10;
    }

    const int ty = tid >> 4, tx = tid & 15;
    const int ck0 = ty * 4, p0 = tx * 4;
    unsigned long long best[4] = {~0ull, ~0ull, ~0ull, ~0ull};

    for (int t = blockIdx.x; t < NT64; t += GXF) {
        const int tb = t * TN;
        __syncthreads();
        {
            int p = tid >> 2, q = tid & 3;
            const float4* row = (const float4*)(x + (size_t)(tb + p) * DIM + q * 16);
#pragma unroll
            for (int i = 0; i < 4; i++) {
                float4 v = row[i];
                int dd = q * 16 + i * 4;
                Xt[(dd + 0) * 68 + p] = v.x;
                Xt[(dd + 1) * 68 + p] = v.y;
                Xt[(dd + 2) * 68 + p] = v.z;
                Xt[(dd + 3) * 68 + p] = v.w;
            }
            if (tid < TN) x2s[tid] = g_x2[tb + tid];
        }
        __syncthreads();

        float S9[4][4] = {}, S10[4][4] = {};
#pragma unroll 2
        for (int dd = 0; dd < DIM; dd++) {
            float4 c9v = *(const float4*)(C9 + dd * TK + ck0);
            float4 cav = *(const float4*)(C10 + dd * TK + ck0);
            float4 xv4 = *(const float4*)(Xt + dd * 68 + p0);
            float a9[4] = {c9v.x, c9v.y, c9v.z, c9v.w};
            float aa[4] = {cav.x, cav.y, cav.z, cav.w};
            float xv[4] = {xv4.x, xv4.y, xv4.z, xv4.w};
#pragma unroll
            for (int i = 0; i < 4; i++)
#pragma unroll
                for (int j = 0; j < 4; j++) {
                    S9[i][j]  = fmaf(a9[i], xv[j], S9[i][j]);
                    S10[i][j] = fmaf(aa[i], xv[j], S10[i][j]);
                }
        }
#pragma unroll
        for (int j = 0; j < 4; j++) {
            float xv2 = x2s[p0 + j];
            unsigned idx = (unsigned)(tb + p0 + j);
#pragma unroll
            for (int i = 0; i < 4; i++) {
                float d2m = fmaf(-2.f, S9[i][j], c29[ck0 + i] + xv2);
                if (d2m < BW2) {
                    float d2 = fmaf(-2.f, S10[i][j], c210[ck0 + i] + xv2);
                    d2 = fmaxf(d2, 0.f);
                    unsigned long long key =
                        ((unsigned long long)__float_as_uint(d2) << 32) | idx;
                    if (key < best[i]) best[i] = key;
                }
            }
        }
    }

#pragma unroll
    for (int i = 0; i < 4; i++) {
        unsigned long long v = best[i];
#pragma unroll
        for (int off = 8; off > 0; off >>= 1) {
            unsigned long long o = __shfl_down_sync(0xffffffffu, v, off, 16);
            if (o < v) v = o;
        }
        if (tx == 0) atomicMin(&g_best[kb + ck0 + i], v);
    }
}

__global__ void zero_out(float* out, int n) {
    int i = blockIdx.x * blockDim.x + threadIdx.x;
    if (i < n) out[i] = 0.f;
}

__global__ void finish_kernel(float* __restrict__ out, const float* __restrict__ x,
                              int out_size) {
    int k = blockIdx.x, d = threadIdx.x;
    if (out_size >= KC * DIM)
        out[k * DIM + d] = g_c[0][k][d];
    unsigned long long b = g_best[k];
    unsigned idx = (b == ~0ull) ? 0u : (unsigned)(b & 0xffffffffu);
    if (out_size >= 2 * KC * DIM)
        out[KC * DIM + k * DIM + d] = x[(size_t)idx * DIM + d];
    if (d == 0 && out_size >= 2 * KC * DIM + KC)
        out[2 * KC * DIM + k] = (float)idx;
}

extern "C" void kernel_launch(void* const* d_in, const int* in_sizes, int n_in,
                              void* d_out, int out_size) {
    const float* x = (const float*)d_in[0];
    const void* seed = d_in[1];
    float* out = (float*)d_out;
    (void)in_sizes; (void)n_in;

    const size_t iterSmem = (size_t)(64 * KB + KB + 64 * XTS + PB * XRS + PB * MSS + PB) * sizeof(float);
    const size_t finalSmem = (size_t)(2 * 64 * 64 + 2 * 64 + 64 * 68 + 64) * sizeof(float);
    cudaFuncSetAttribute(iter_kernel,  cudaFuncAttributeMaxDynamicSharedMemorySize, (int)iterSmem);
    cudaFuncSetAttribute(final_kernel, cudaFuncAttributeMaxDynamicSharedMemorySize, (int)finalSmem);

    x2_kernel<<<(NPTS + 255) / 256, 256>>>(x);
    detect_kernel<<<1, 128>>>(seed);
    seed_kernel<<<KC, DIM>>>(x, seed);

    for (int it = 0; it < ITERS; it++) {
        iter_kernel<<<dim3(GXI, KC / KB), 256, iterSmem>>>(x, it);
        update_kernel<<<KC, DIM>>>(it);
    }

    final_kernel<<<dim3(GXF, KC / TK), 256, finalSmem>>>(x);

    if (out_size > 0)
        zero_out<<<(out_size + 255) / 256, 256>>>(out, out_size);
    finish_kernel<<<KC, DIM>>>(out, x, out_size);
}

// round 5
// speedup vs baseline: 1.7213x; 1.3803x over previous
#include <cuda_runtime.h>
#include <cuda_bf16.h>
#include <stdint.h>

#define NPTS 200000
#define DIM 64
#define KC 256
#define BW2 144.0f
#define ITERS 10

#define KB 128
#define PB 128
#define NT128 1563
#define GXI 74
#define XTS 132
#define XRS 68
#define MSS 132

#define TK 64
#define TN 64
#define NT64 3125
#define GXF 111

typedef unsigned long long u64p;
#define PK2(d, lo, hi) asm("mov.b64 %0, {%1, %2};" : "=l"(d) : "f"(lo), "f"(hi))
#define UPK2(lo, hi, s) asm("mov.b64 {%0, %1}, %2;" : "=f"(lo), "=f"(hi) : "l"(s))
#define FMA2(d, a, b, c) asm("fma.rn.f32x2 %0, %1, %2, %3;" : "=l"(d) : "l"(a), "l"(b), "l"(c))
#define ADD2(d, a, b) asm("add.rn.f32x2 %0, %1, %2;" : "=l"(d) : "l"(a), "l"(b))

__device__ float g_c[2][KC][DIM];
__device__ float g_acc[KC][DIM];      // per-center exception sums
__device__ float g_cnt[KC];           // per-center exception counts
__device__ double g_sumx[DIM];        // global sum of all points (fp64)
__device__ float g_x2[NPTS];
__device__ unsigned long long g_best[KC];
__device__ int g_seed64;

// ---------------------------------------------------------------- utilities

__global__ void x2_kernel(const float* __restrict__ x) {
    int n = blockIdx.x * blockDim.x + threadIdx.x;
    if (n >= NPTS) return;
    const float4* r = (const float4*)(x + (size_t)n * DIM);
    float s = 0.f;
#pragma unroll
    for (int i = 0; i < DIM / 4; i++) {
        float4 v = r[i];
        s = fmaf(v.x, v.x, s); s = fmaf(v.y, v.y, s);
        s = fmaf(v.z, v.z, s); s = fmaf(v.w, v.w, s);
    }
    g_x2[n] = s;
}

__global__ void detect_kernel(const void* __restrict__ seed) {
    __shared__ int bad;
    if (threadIdx.x == 0) bad = 0;
    __syncthreads();
    unsigned long long v = ((const unsigned long long*)seed)[threadIdx.x];
    if (v >= (unsigned long long)NPTS) atomicOr(&bad, 1);
    __syncthreads();
    if (threadIdx.x == 0) g_seed64 = bad ? 0 : 1;
}

__global__ void seed_kernel(const float* __restrict__ x, const void* __restrict__ seedraw) {
    int k = blockIdx.x, d = threadIdx.x;
    long long idx;
    if (g_seed64) idx = ((const long long*)seedraw)[k];
    else          idx = (long long)(((const int*)seedraw)[k]);
    g_c[0][k][d] = x[idx * DIM + d];
    g_acc[k][d] = 0.f;
    if (d == 0) { g_cnt[k] = 0.f; g_best[k] = ~0ull; }
}

__global__ void zero_sum_kernel() {
    if (threadIdx.x < DIM) g_sumx[threadIdx.x] = 0.0;
}

// S_all[d] = sum over all points of x[p][d]; fp32 block partials + fp64 atomics
__global__ void sum_kernel(const float* __restrict__ x) {
    __shared__ float part[4][DIM];
    int d = threadIdx.x & 63, r = threadIdx.x >> 6;
    float s = 0.f;
    for (int p = blockIdx.x * 4 + r; p < NPTS; p += gridDim.x * 4)
        s += x[(size_t)p * DIM + d];
    part[r][d] = s;
    __syncthreads();
    if (r == 0) {
        double tot = (double)part[0][d] + (double)part[1][d]
                   + (double)part[2][d] + (double)part[3][d];
        atomicAdd(&g_sumx[d], tot);
    }
}

__global__ void update_kernel(int it) {
    int k = blockIdx.x, d = threadIdx.x;
    double cnt = (double)NPTS - (double)g_cnt[k];
    double v = (g_sumx[d] - (double)g_acc[k][d]) / cnt;
    __syncthreads();
    g_c[(it + 1) & 1][k][d] = (float)v;
    g_acc[k][d] = 0.f;
    if (d == 0) g_cnt[k] = 0.f;
}

// ------------------------------------------- sparse-complement mean-shift iteration
// Phase 1: dense dot GEMM (f32x2). Exceptions (d2 >= BW2) recorded as bits.
// Phase 2 (dense exception GEMM) runs ONLY for tiles with >=1 exception.

__global__ void __launch_bounds__(256, 1) iter_kernel(const float* __restrict__ x, int it) {
    extern __shared__ float smem[];
    float* Cs  = smem;              // [64][128]
    float* c2s = Cs + 64 * KB;      // [128]
    float* Xt  = c2s + KB;          // [64][132]
    float* Xr  = Xt + 64 * XTS;     // [128][68]  (filled only for flagged tiles)
    float* Ms  = Xr + PB * XRS;     // [128][132] exception mask, swizzled
    float* x2s = Ms + PB * MSS;     // [128]
    int* flagp = (int*)(x2s + PB);

    const int tid = threadIdx.x;
    const int ty = tid >> 4, tx = tid & 15;
    const int ck0 = ty * 8, p0 = tx * 8, dq = tx * 4;
    const int kb = blockIdx.y * KB;
    const float* cin = &g_c[it & 1][0][0];

    for (int e = tid; e < KB * DIM; e += 256) {
        int ck = e & (KB - 1), d = e >> 7;
        Cs[d * KB + ck] = cin[(size_t)(kb + ck) * DIM + d];
    }
    __syncthreads();
    if (tid < KB) {
        float s = 0.f;
#pragma unroll
        for (int d = 0; d < DIM; d++) { float c = Cs[d * KB + tid]; s = fmaf(c, c, s); }
        c2s[tid] = s;
    }
    __syncthreads();

    u64p c2d[8];
#pragma unroll
    for (int i = 0; i < 8; i++) { float v = c2s[ck0 + i]; PK2(c2d[i], v, v); }
    u64p neg2; { float m2 = -2.0f; PK2(neg2, m2, m2); }

    u64p acc2[4][4];
#pragma unroll
    for (int i = 0; i < 4; i++)
#pragma unroll
        for (int j = 0; j < 4; j++) acc2[i][j] = 0ull;
    int cnti[8] = {0, 0, 0, 0, 0, 0, 0, 0};

    for (int t = blockIdx.x; t < NT128; t += GXI) {
        const int tb = t * PB;
        __syncthreads();                 // prev tile consumers done
        if (tid == 0) *flagp = 0;
        {   // load x tile -> Xt (transposed) + x2s  (Xr deferred; flagged-only)
            int ploc = tid & 127, d0 = (tid >> 7) * 32;
            bool valid = (tb + ploc) < NPTS;
            const float4* src = (const float4*)(x + (size_t)(tb + ploc) * DIM + d0);
#pragma unroll
            for (int k = 0; k < 8; k++) {
                float4 v = valid ? src[k] : make_float4(0.f, 0.f, 0.f, 0.f);
                Xt[(d0 + 4 * k + 0) * XTS + ploc] = v.x;
                Xt[(d0 + 4 * k + 1) * XTS + ploc] = v.y;
                Xt[(d0 + 4 * k + 2) * XTS + ploc] = v.z;
                Xt[(d0 + 4 * k + 3) * XTS + ploc] = v.w;
            }
            // phantom points get x2 = -1e30 -> d2 << BW2 -> NOT an exception
            if (tid < PB) x2s[tid] = ((tb + tid) < NPTS) ? g_x2[tb + tid] : -1e30f;
        }
        __syncthreads();

        // phase 1: dots (pairs along points)
        u64p S2[8][4];
#pragma unroll
        for (int i = 0; i < 8; i++)
#pragma unroll
            for (int j = 0; j < 4; j++) S2[i][j] = 0ull;

#pragma unroll 8
        for (int dd = 0; dd < DIM; dd++) {
            float4 ca = *(const float4*)(Cs + dd * KB + ck0);
            float4 cb = *(const float4*)(Cs + dd * KB + ck0 + 4);
            float4 xa = *(const float4*)(Xt + dd * XTS + p0);
            float4 xb = *(const float4*)(Xt + dd * XTS + p0 + 4);
            u64p xp[4];
            PK2(xp[0], xa.x, xa.y); PK2(xp[1], xa.z, xa.w);
            PK2(xp[2], xb.x, xb.y); PK2(xp[3], xb.z, xb.w);
            float cv[8] = {ca.x, ca.y, ca.z, ca.w, cb.x, cb.y, cb.z, cb.w};
#pragma unroll
            for (int i = 0; i < 8; i++) {
                u64p cd; PK2(cd, cv[i], cv[i]);
#pragma unroll
                for (int j = 0; j < 4; j++) FMA2(S2[i][j], cd, xp[j], S2[i][j]);
            }
        }

        // epilogue: exception bits (bit = i*8 + j; i center slot, j point slot)
        unsigned long long bits = 0ull;
#pragma unroll
        for (int jp = 0; jp < 4; jp++) {
            u64p x2p; PK2(x2p, x2s[p0 + 2 * jp], x2s[p0 + 2 * jp + 1]);
#pragma unroll
            for (int i = 0; i < 8; i++) {
                u64p tsum; ADD2(tsum, c2d[i], x2p);
                u64p d2;   FMA2(d2, neg2, S2[i][jp], tsum);
                float dlo, dhi; UPK2(dlo, dhi, d2);
                if (!(dlo < BW2)) bits |= 1ull << (i * 8 + 2 * jp);
                if (!(dhi < BW2)) bits |= 1ull << (i * 8 + 2 * jp + 1);
            }
        }
#pragma unroll
        for (int i = 0; i < 8; i++)
            cnti[i] += __popc((unsigned)((bits >> (i * 8)) & 0xFFull));

        unsigned bal = __ballot_sync(0xffffffffu, bits != 0ull);
        if (bal != 0u && (tid & 31) == 0) atomicOr(flagp, 1);
        __syncthreads();

        if (*flagp) {
            // stage Xr from global (rare path) + write exception-mask floats
            {
                int ploc = tid & 127, d0 = (tid >> 7) * 32;
                bool valid = (tb + ploc) < NPTS;
                const float4* src = (const float4*)(x + (size_t)(tb + ploc) * DIM + d0);
#pragma unroll
                for (int k = 0; k < 8; k++) {
                    float4 v = valid ? src[k] : make_float4(0.f, 0.f, 0.f, 0.f);
                    *(float4*)(Xr + ploc * XRS + d0 + 4 * k) = v;
                }
            }
            const int sw = tx & 7;
            const int colA = 4 * ((2 * ty) ^ sw);
            const int colB = 4 * ((2 * ty + 1) ^ sw);
#pragma unroll
            for (int jp = 0; jp < 4; jp++) {
                int j0 = 2 * jp, j1 = 2 * jp + 1;
                float4 a0, b0, a1, b1;
                a0.x = (float)((bits >> (0 * 8 + j0)) & 1ull);
                a0.y = (float)((bits >> (1 * 8 + j0)) & 1ull);
                a0.z = (float)((bits >> (2 * 8 + j0)) & 1ull);
                a0.w = (float)((bits >> (3 * 8 + j0)) & 1ull);
                b0.x = (float)((bits >> (4 * 8 + j0)) & 1ull);
                b0.y = (float)((bits >> (5 * 8 + j0)) & 1ull);
                b0.z = (float)((bits >> (6 * 8 + j0)) & 1ull);
                b0.w = (float)((bits >> (7 * 8 + j0)) & 1ull);
                a1.x = (float)((bits >> (0 * 8 + j1)) & 1ull);
                a1.y = (float)((bits >> (1 * 8 + j1)) & 1ull);
                a1.z = (float)((bits >> (2 * 8 + j1)) & 1ull);
                a1.w = (float)((bits >> (3 * 8 + j1)) & 1ull);
                b1.x = (float)((bits >> (4 * 8 + j1)) & 1ull);
                b1.y = (float)((bits >> (5 * 8 + j1)) & 1ull);
                b1.z = (float)((bits >> (6 * 8 + j1)) & 1ull);
                b1.w = (float)((bits >> (7 * 8 + j1)) & 1ull);
                int pA = p0 + j0, pB = p0 + j1;
                *(float4*)(Ms + pA * MSS + colA) = a0;
                *(float4*)(Ms + pA * MSS + colB) = b0;
                *(float4*)(Ms + pB * MSS + colA) = a1;
                *(float4*)(Ms + pB * MSS + colB) = b1;
            }
            __syncthreads();

            // phase 2: Sigma_exc[ck][d] += M_exc[p][ck] * X[p][d]
#pragma unroll 4
            for (int p = 0; p < PB; p++) {
                const int sw2 = (p >> 3) & 7;
                float4 ma = *(const float4*)(Ms + p * MSS + 4 * ((2 * ty) ^ sw2));
                float4 mb = *(const float4*)(Ms + p * MSS + 4 * ((2 * ty + 1) ^ sw2));
                float4 xv = *(const float4*)(Xr + p * XRS + dq);
                u64p mp[4];
                PK2(mp[0], ma.x, ma.y); PK2(mp[1], ma.z, ma.w);
                PK2(mp[2], mb.x, mb.y); PK2(mp[3], mb.z, mb.w);
                u64p xd[4];
                PK2(xd[0], xv.x, xv.x); PK2(xd[1], xv.y, xv.y);
                PK2(xd[2], xv.z, xv.z); PK2(xd[3], xv.w, xv.w);
#pragma unroll
                for (int i2 = 0; i2 < 4; i2++)
#pragma unroll
                    for (int j = 0; j < 4; j++) FMA2(acc2[i2][j], mp[i2], xd[j], acc2[i2][j]);
            }
        }
    }

#pragma unroll
    for (int i2 = 0; i2 < 4; i2++)
#pragma unroll
        for (int j = 0; j < 4; j++) {
            float alo, ahi; UPK2(alo, ahi, acc2[i2][j]);
            atomicAdd(&g_acc[kb + ck0 + 2 * i2 + 0][dq + j], alo);
            atomicAdd(&g_acc[kb + ck0 + 2 * i2 + 1][dq + j], ahi);
        }
#pragma unroll
    for (int i = 0; i < 8; i++) {
        float v = (float)cnti[i];
#pragma unroll
        for (int off = 8; off > 0; off >>= 1)
            v += __shfl_down_sync(0xffffffffu, v, off, 16);
        if (tx == 0) atomicAdd(&g_cnt[kb + ck0 + i], v);
    }
}

// ------------------------------------------- final masked argmin (proven scalar fp32)

__global__ void __launch_bounds__(256) final_kernel(const float* __restrict__ x) {
    extern __shared__ float smem[];
    float* C9   = smem;
    float* C10  = C9 + 64 * 64;
    float* c29  = C10 + 64 * 64;
    float* c210 = c29 + 64;
    float* Xt   = c210 + 64;
    float* x2s  = Xt + 64 * 68;

    const int tid = threadIdx.x;
    const int kb  = blockIdx.y * TK;

    {
        int ck = tid >> 2, q = tid & 3;
        const float4* r9  = (const float4*)(&g_c[1][kb + ck][0] + q * 16);
        const float4* r10 = (const float4*)(&g_c[0][kb + ck][0] + q * 16);
#pragma unroll
        for (int i = 0; i < 4; i++) {
            float4 a = r9[i], b = r10[i];
            int dd = q * 16 + i * 4;
            C9[(dd + 0) * TK + ck] = a.x; C9[(dd + 1) * TK + ck] = a.y;
            C9[(dd + 2) * TK + ck] = a.z; C9[(dd + 3) * TK + ck] = a.w;
            C10[(dd + 0) * TK + ck] = b.x; C10[(dd + 1) * TK + ck] = b.y;
            C10[(dd + 2) * TK + ck] = b.z; C10[(dd + 3) * TK + ck] = b.w;
        }
    }
    __syncthreads();
    if (tid < TK) {
        float s9 = 0.f, s10 = 0.f;
#pragma unroll
        for (int d = 0; d < DIM; d++) {
            float a = C9[d * TK + tid];  s9  = fmaf(a, a, s9);
            float b = C10[d * TK + tid]; s10 = fmaf(b, b, s10);
        }
        c29[tid] = s9; c210[tid] = s10;
    }

    const int ty = tid >> 4, tx = tid & 15;
    const int ck0 = ty * 4, p0 = tx * 4;
    unsigned long long best[4] = {~0ull, ~0ull, ~0ull, ~0ull};

    for (int t = blockIdx.x; t < NT64; t += GXF) {
        const int tb = t * TN;
        __syncthreads();
        {
            int p = tid >> 2, q = tid & 3;
            const float4* row = (const float4*)(x + (size_t)(tb + p) * DIM + q * 16);
#pragma unroll
            for (int i = 0; i < 4; i++) {
                float4 v = row[i];
                int dd = q * 16 + i * 4;
                Xt[(dd + 0) * 68 + p] = v.x;
                Xt[(dd + 1) * 68 + p] = v.y;
                Xt[(dd + 2) * 68 + p] = v.z;
                Xt[(dd + 3) * 68 + p] = v.w;
            }
            if (tid < TN) x2s[tid] = g_x2[tb + tid];
        }
        __syncthreads();

        float S9[4][4] = {}, S10[4][4] = {};
#pragma unroll 2
        for (int dd = 0; dd < DIM; dd++) {
            float4 c9v = *(const float4*)(C9 + dd * TK + ck0);
            float4 cav = *(const float4*)(C10 + dd * TK + ck0);
            float4 xv4 = *(const float4*)(Xt + dd * 68 + p0);
            float a9[4] = {c9v.x, c9v.y, c9v.z, c9v.w};
            float aa[4] = {cav.x, cav.y, cav.z, cav.w};
            float xv[4] = {xv4.x, xv4.y, xv4.z, xv4.w};
#pragma unroll
            for (int i = 0; i < 4; i++)
#pragma unroll
                for (int j = 0; j < 4; j++) {
                    S9[i][j]  = fmaf(a9[i], xv[j], S9[i][j]);
                    S10[i][j] = fmaf(aa[i], xv[j], S10[i][j]);
                }
        }
#pragma unroll
        for (int j = 0; j < 4; j++) {
            float xv2 = x2s[p0 + j];
            unsigned idx = (unsigned)(tb + p0 + j);
#pragma unroll
            for (int i = 0; i < 4; i++) {
                float d2m = fmaf(-2.f, S9[i][j], c29[ck0 + i] + xv2);
                if (d2m < BW2) {
                    float d2 = fmaf(-2.f, S10[i][j], c210[ck0 + i] + xv2);
                    d2 = fmaxf(d2, 0.f);
                    unsigned long long key =
                        ((unsigned long long)__float_as_uint(d2) << 32) | idx;
                    if (key < best[i]) best[i] = key;
                }
            }
        }
    }

#pragma unroll
    for (int i = 0; i < 4; i++) {
        unsigned long long v = best[i];
#pragma unroll
        for (int off = 8; off > 0; off >>= 1) {
            unsigned long long o = __shfl_down_sync(0xffffffffu, v, off, 16);
            if (o < v) v = o;
        }
        if (tx == 0) atomicMin(&g_best[kb + ck0 + i], v);
    }
}

// ---------------------------------------------------------------- epilogue

__global__ void zero_out(float* out, int n) {
    int i = blockIdx.x * blockDim.x + threadIdx.x;
    if (i < n) out[i] = 0.f;
}

__global__ void finish_kernel(float* __restrict__ out, const float* __restrict__ x,
                              int out_size) {
    int k = blockIdx.x, d = threadIdx.x;
    if (out_size >= KC * DIM)
        out[k * DIM + d] = g_c[0][k][d];
    unsigned long long b = g_best[k];
    unsigned idx = (b == ~0ull) ? 0u : (unsigned)(b & 0xffffffffu);
    if (out_size >= 2 * KC * DIM)
        out[KC * DIM + k * DIM + d] = x[(size_t)idx * DIM + d];
    if (d == 0 && out_size >= 2 * KC * DIM + KC)
        out[2 * KC * DIM + k] = (float)idx;
}

// ---------------------------------------------------------------- launcher

extern "C" void kernel_launch(void* const* d_in, const int* in_sizes, int n_in,
                              void* d_out, int out_size) {
    const float* x = (const float*)d_in[0];
    const void* seed = d_in[1];
    float* out = (float*)d_out;
    (void)in_sizes; (void)n_in;

    const size_t iterSmem = (size_t)(64 * KB + KB + 64 * XTS + PB * XRS + PB * MSS + PB + 16)
                            * sizeof(float);
    const size_t finalSmem = (size_t)(2 * 64 * 64 + 2 * 64 + 64 * 68 + 64) * sizeof(float);
    cudaFuncSetAttribute(iter_kernel,  cudaFuncAttributeMaxDynamicSharedMemorySize, (int)iterSmem);
    cudaFuncSetAttribute(final_kernel, cudaFuncAttributeMaxDynamicSharedMemorySize, (int)finalSmem);

    x2_kernel<<<(NPTS + 255) / 256, 256>>>(x);
    detect_kernel<<<1, 128>>>(seed);
    seed_kernel<<<KC, DIM>>>(x, seed);
    zero_sum_kernel<<<1, 64>>>();
    sum_kernel<<<128, 256>>>(x);

    for (int it = 0; it < ITERS; it++) {
        iter_kernel<<<dim3(GXI, KC / KB), 256, iterSmem>>>(x, it);
        update_kernel<<<KC, DIM>>>(it);
    }

    final_kernel<<<dim3(GXF, KC / TK), 256, finalSmem>>>(x);

    if (out_size > 0)
        zero_out<<<(out_size + 255) / 256, 256>>>(out, out_size);
    finish_kernel<<<KC, DIM>>>(out, x, out_size);
}

// round 6
// speedup vs baseline: 4.1821x; 2.4297x over previous
#include <cuda_runtime.h>
#include <cuda_bf16.h>
#include <stdint.h>

#define NPTS 200000
#define DIM 64
#define KC 256
#define BW2 144.0f
#define ITERS 10

#define KB 128
#define PB 128
#define NT128 1563
#define GXI 74
#define XTS 132
#define XRS 68
#define MSS 132

#define TK 64
#define TN 64
#define NT64 3125
#define GXF 111

typedef unsigned long long u64p;
#define PK2(d, lo, hi) asm("mov.b64 %0, {%1, %2};" : "=l"(d) : "f"(lo), "f"(hi))
#define UPK2(lo, hi, s) asm("mov.b64 {%0, %1}, %2;" : "=f"(lo), "=f"(hi) : "l"(s))
#define FMA2(d, a, b, c) asm("fma.rn.f32x2 %0, %1, %2, %3;" : "=l"(d) : "l"(a), "l"(b), "l"(c))
#define ADD2(d, a, b) asm("add.rn.f32x2 %0, %1, %2;" : "=l"(d) : "l"(a), "l"(b))

__device__ float g_c[2][KC][DIM];
__device__ float g_acc[KC][DIM];      // exception sums
__device__ float g_cnt[KC];           // exception counts
__device__ double g_sumx[DIM];        // global sum of all points
__device__ float g_x2[NPTS];
__device__ unsigned long long g_best[KC];
__device__ int g_seed64;
__device__ float g_cmax;              // max center norm (+eps)
__device__ int g_tileflag[NT64];      // final-pass tiles needing mask recompute

// ---------------------------------------------------------------- utilities

__global__ void x2_kernel(const float* __restrict__ x) {
    int n = blockIdx.x * blockDim.x + threadIdx.x;
    if (n >= NPTS) return;
    const float4* r = (const float4*)(x + (size_t)n * DIM);
    float s = 0.f;
#pragma unroll
    for (int i = 0; i < DIM / 4; i++) {
        float4 v = r[i];
        s = fmaf(v.x, v.x, s); s = fmaf(v.y, v.y, s);
        s = fmaf(v.z, v.z, s); s = fmaf(v.w, v.w, s);
    }
    g_x2[n] = s;
    if (n < NT64) g_tileflag[n] = 0;
}

__global__ void detect_kernel(const void* __restrict__ seed) {
    __shared__ int bad;
    if (threadIdx.x == 0) bad = 0;
    __syncthreads();
    unsigned long long v = ((const unsigned long long*)seed)[threadIdx.x];
    if (v >= (unsigned long long)NPTS) atomicOr(&bad, 1);
    __syncthreads();
    if (threadIdx.x == 0) g_seed64 = bad ? 0 : 1;
}

__global__ void seed_kernel(const float* __restrict__ x, const void* __restrict__ seedraw) {
    int k = blockIdx.x, d = threadIdx.x;
    long long idx;
    if (g_seed64) idx = ((const long long*)seedraw)[k];
    else          idx = (long long)(((const int*)seedraw)[k]);
    g_c[0][k][d] = x[idx * DIM + d];
    g_acc[k][d] = 0.f;
    if (d == 0) { g_cnt[k] = 0.f; g_best[k] = ~0ull; }
}

__global__ void zero_sum_kernel() {
    if (threadIdx.x < DIM) g_sumx[threadIdx.x] = 0.0;
}

__global__ void sum_kernel(const float* __restrict__ x) {
    __shared__ float part[4][DIM];
    int d = threadIdx.x & 63, r = threadIdx.x >> 6;
    float s = 0.f;
    for (int p = blockIdx.x * 4 + r; p < NPTS; p += gridDim.x * 4)
        s += x[(size_t)p * DIM + d];
    part[r][d] = s;
    __syncthreads();
    if (r == 0) {
        double tot = (double)part[0][d] + (double)part[1][d]
                   + (double)part[2][d] + (double)part[3][d];
        atomicAdd(&g_sumx[d], tot);
    }
}

__global__ void update_kernel(int it) {
    int k = blockIdx.x, d = threadIdx.x;
    double cnt = (double)NPTS - (double)g_cnt[k];
    double v = (g_sumx[d] - (double)g_acc[k][d]) / cnt;
    __syncthreads();
    g_c[(it + 1) & 1][k][d] = (float)v;
    g_acc[k][d] = 0.f;
    if (d == 0) g_cnt[k] = 0.f;
}

// max center norm of buffer buf -> g_cmax (conservative, +eps)
__global__ void cmax_kernel(int buf) {
    __shared__ float red[KC];
    int k = threadIdx.x;
    const float4* cr = (const float4*)&g_c[buf][k][0];
    float c2 = 0.f;
#pragma unroll
    for (int q = 0; q < 16; q++) {
        float4 v = cr[q];
        c2 = fmaf(v.x, v.x, c2); c2 = fmaf(v.y, v.y, c2);
        c2 = fmaf(v.z, v.z, c2); c2 = fmaf(v.w, v.w, c2);
    }
    red[k] = c2;
    __syncthreads();
    for (int s = 128; s > 0; s >>= 1) {
        if (k < s) red[k] = fmaxf(red[k], red[k + s]);
        __syncthreads();
    }
    if (k == 0) g_cmax = sqrtf(red[0]) + 1e-3f;
}

// ------------------------------------------- sparse iteration (its 2..10)
// Candidate filter (exact, triangle inequality): point can be an exception
// for SOME center only if |x| >= 12 - cmax. Candidates get a full exact
// scalar check against all 256 centers. record!=0 also flags 64-pt tiles
// containing candidates (for the final pass's mask recompute).

__global__ void __launch_bounds__(256) sparse_iter(const float* __restrict__ x,
                                                   int it, int record) {
    const float cmax = g_cmax;
    float tthr = 12.0f - cmax - 1e-3f;
    const float thr2 = (tthr > 0.f) ? tthr * tthr : -1.0f;
    const float* cc = &g_c[it & 1][0][0];
    const int stride = gridDim.x * blockDim.x;

    for (int n = blockIdx.x * blockDim.x + threadIdx.x; n < NPTS; n += stride) {
        const float x2 = g_x2[n];
        if (x2 < thr2) continue;
        if (record) g_tileflag[n >> 6] = 1;

        float xv[DIM];
        const float4* xr = (const float4*)(x + (size_t)n * DIM);
#pragma unroll
        for (int q = 0; q < 16; q++) {
            float4 v = xr[q];
            xv[4 * q + 0] = v.x; xv[4 * q + 1] = v.y;
            xv[4 * q + 2] = v.z; xv[4 * q + 3] = v.w;
        }
        for (int k = 0; k < KC; k++) {
            const float4* cr = (const float4*)(cc + (size_t)k * DIM);
            float dot = 0.f, c2 = 0.f;
#pragma unroll
            for (int q = 0; q < 16; q++) {
                float4 cv = cr[q];
                dot = fmaf(cv.x, xv[4 * q + 0], dot);
                dot = fmaf(cv.y, xv[4 * q + 1], dot);
                dot = fmaf(cv.z, xv[4 * q + 2], dot);
                dot = fmaf(cv.w, xv[4 * q + 3], dot);
                c2 = fmaf(cv.x, cv.x, c2); c2 = fmaf(cv.y, cv.y, c2);
                c2 = fmaf(cv.z, cv.z, c2); c2 = fmaf(cv.w, cv.w, c2);
            }
            float d2 = c2 + x2 - 2.f * dot;
            if (!(d2 < BW2)) {
                atomicAdd(&g_cnt[k], 1.0f);
#pragma unroll
                for (int d = 0; d < DIM; d++) atomicAdd(&g_acc[k][d], xv[d]);
            }
        }
    }
}

// ------------------------------------------- dense iteration (it=0 only)
// Proven round-5 kernel: dense f32x2 dot GEMM; exception GEMM per flagged tile.

__global__ void __launch_bounds__(256, 1) iter_kernel(const float* __restrict__ x, int it) {
    extern __shared__ float smem[];
    float* Cs  = smem;
    float* c2s = Cs + 64 * KB;
    float* Xt  = c2s + KB;
    float* Xr  = Xt + 64 * XTS;
    float* Ms  = Xr + PB * XRS;
    float* x2s = Ms + PB * MSS;
    int* flagp = (int*)(x2s + PB);

    const int tid = threadIdx.x;
    const int ty = tid >> 4, tx = tid & 15;
    const int ck0 = ty * 8, p0 = tx * 8, dq = tx * 4;
    const int kb = blockIdx.y * KB;
    const float* cin = &g_c[it & 1][0][0];

    for (int e = tid; e < KB * DIM; e += 256) {
        int ck = e & (KB - 1), d = e >> 7;
        Cs[d * KB + ck] = cin[(size_t)(kb + ck) * DIM + d];
    }
    __syncthreads();
    if (tid < KB) {
        float s = 0.f;
#pragma unroll
        for (int d = 0; d < DIM; d++) { float c = Cs[d * KB + tid]; s = fmaf(c, c, s); }
        c2s[tid] = s;
    }
    __syncthreads();

    u64p c2d[8];
#pragma unroll
    for (int i = 0; i < 8; i++) { float v = c2s[ck0 + i]; PK2(c2d[i], v, v); }
    u64p neg2; { float m2 = -2.0f; PK2(neg2, m2, m2); }

    u64p acc2[4][4];
#pragma unroll
    for (int i = 0; i < 4; i++)
#pragma unroll
        for (int j = 0; j < 4; j++) acc2[i][j] = 0ull;
    int cnti[8] = {0, 0, 0, 0, 0, 0, 0, 0};

    for (int t = blockIdx.x; t < NT128; t += GXI) {
        const int tb = t * PB;
        __syncthreads();
        if (tid == 0) *flagp = 0;
        {
            int ploc = tid & 127, d0 = (tid >> 7) * 32;
            bool valid = (tb + ploc) < NPTS;
            const float4* src = (const float4*)(x + (size_t)(tb + ploc) * DIM + d0);
#pragma unroll
            for (int k = 0; k < 8; k++) {
                float4 v = valid ? src[k] : make_float4(0.f, 0.f, 0.f, 0.f);
                Xt[(d0 + 4 * k + 0) * XTS + ploc] = v.x;
                Xt[(d0 + 4 * k + 1) * XTS + ploc] = v.y;
                Xt[(d0 + 4 * k + 2) * XTS + ploc] = v.z;
                Xt[(d0 + 4 * k + 3) * XTS + ploc] = v.w;
            }
            if (tid < PB) x2s[tid] = ((tb + tid) < NPTS) ? g_x2[tb + tid] : -1e30f;
        }
        __syncthreads();

        u64p S2[8][4];
#pragma unroll
        for (int i = 0; i < 8; i++)
#pragma unroll
            for (int j = 0; j < 4; j++) S2[i][j] = 0ull;

#pragma unroll 8
        for (int dd = 0; dd < DIM; dd++) {
            float4 ca = *(const float4*)(Cs + dd * KB + ck0);
            float4 cb = *(const float4*)(Cs + dd * KB + ck0 + 4);
            float4 xa = *(const float4*)(Xt + dd * XTS + p0);
            float4 xb = *(const float4*)(Xt + dd * XTS + p0 + 4);
            u64p xp[4];
            PK2(xp[0], xa.x, xa.y); PK2(xp[1], xa.z, xa.w);
            PK2(xp[2], xb.x, xb.y); PK2(xp[3], xb.z, xb.w);
            float cv[8] = {ca.x, ca.y, ca.z, ca.w, cb.x, cb.y, cb.z, cb.w};
#pragma unroll
            for (int i = 0; i < 8; i++) {
                u64p cd; PK2(cd, cv[i], cv[i]);
#pragma unroll
                for (int j = 0; j < 4; j++) FMA2(S2[i][j], cd, xp[j], S2[i][j]);
            }
        }

        unsigned long long bits = 0ull;
#pragma unroll
        for (int jp = 0; jp < 4; jp++) {
            u64p x2p; PK2(x2p, x2s[p0 + 2 * jp], x2s[p0 + 2 * jp + 1]);
#pragma unroll
            for (int i = 0; i < 8; i++) {
                u64p tsum; ADD2(tsum, c2d[i], x2p);
                u64p d2;   FMA2(d2, neg2, S2[i][jp], tsum);
                float dlo, dhi; UPK2(dlo, dhi, d2);
                if (!(dlo < BW2)) bits |= 1ull << (i * 8 + 2 * jp);
                if (!(dhi < BW2)) bits |= 1ull << (i * 8 + 2 * jp + 1);
            }
        }
#pragma unroll
        for (int i = 0; i < 8; i++)
            cnti[i] += __popc((unsigned)((bits >> (i * 8)) & 0xFFull));

        unsigned bal = __ballot_sync(0xffffffffu, bits != 0ull);
        if (bal != 0u && (tid & 31) == 0) atomicOr(flagp, 1);
        __syncthreads();

        if (*flagp) {
            {
                int ploc = tid & 127, d0 = (tid >> 7) * 32;
                bool valid = (tb + ploc) < NPTS;
                const float4* src = (const float4*)(x + (size_t)(tb + ploc) * DIM + d0);
#pragma unroll
                for (int k = 0; k < 8; k++) {
                    float4 v = valid ? src[k] : make_float4(0.f, 0.f, 0.f, 0.f);
                    *(float4*)(Xr + ploc * XRS + d0 + 4 * k) = v;
                }
            }
            const int sw = tx & 7;
            const int colA = 4 * ((2 * ty) ^ sw);
            const int colB = 4 * ((2 * ty + 1) ^ sw);
#pragma unroll
            for (int jp = 0; jp < 4; jp++) {
                int j0 = 2 * jp, j1 = 2 * jp + 1;
                float4 a0, b0, a1, b1;
                a0.x = (float)((bits >> (0 * 8 + j0)) & 1ull);
                a0.y = (float)((bits >> (1 * 8 + j0)) & 1ull);
                a0.z = (float)((bits >> (2 * 8 + j0)) & 1ull);
                a0.w = (float)((bits >> (3 * 8 + j0)) & 1ull);
                b0.x = (float)((bits >> (4 * 8 + j0)) & 1ull);
                b0.y = (float)((bits >> (5 * 8 + j0)) & 1ull);
                b0.z = (float)((bits >> (6 * 8 + j0)) & 1ull);
                b0.w = (float)((bits >> (7 * 8 + j0)) & 1ull);
                a1.x = (float)((bits >> (0 * 8 + j1)) & 1ull);
                a1.y = (float)((bits >> (1 * 8 + j1)) & 1ull);
                a1.z = (float)((bits >> (2 * 8 + j1)) & 1ull);
                a1.w = (float)((bits >> (3 * 8 + j1)) & 1ull);
                b1.x = (float)((bits >> (4 * 8 + j1)) & 1ull);
                b1.y = (float)((bits >> (5 * 8 + j1)) & 1ull);
                b1.z = (float)((bits >> (6 * 8 + j1)) & 1ull);
                b1.w = (float)((bits >> (7 * 8 + j1)) & 1ull);
                int pA = p0 + j0, pB = p0 + j1;
                *(float4*)(Ms + pA * MSS + colA) = a0;
                *(float4*)(Ms + pA * MSS + colB) = b0;
                *(float4*)(Ms + pB * MSS + colA) = a1;
                *(float4*)(Ms + pB * MSS + colB) = b1;
            }
            __syncthreads();

#pragma unroll 4
            for (int p = 0; p < PB; p++) {
                const int sw2 = (p >> 3) & 7;
                float4 ma = *(const float4*)(Ms + p * MSS + 4 * ((2 * ty) ^ sw2));
                float4 mb = *(const float4*)(Ms + p * MSS + 4 * ((2 * ty + 1) ^ sw2));
                float4 xv = *(const float4*)(Xr + p * XRS + dq);
                u64p mp[4];
                PK2(mp[0], ma.x, ma.y); PK2(mp[1], ma.z, ma.w);
                PK2(mp[2], mb.x, mb.y); PK2(mp[3], mb.z, mb.w);
                u64p xd[4];
                PK2(xd[0], xv.x, xv.x); PK2(xd[1], xv.y, xv.y);
                PK2(xd[2], xv.z, xv.z); PK2(xd[3], xv.w, xv.w);
#pragma unroll
                for (int i2 = 0; i2 < 4; i2++)
#pragma unroll
                    for (int j = 0; j < 4; j++) FMA2(acc2[i2][j], mp[i2], xd[j], acc2[i2][j]);
            }
        }
    }

#pragma unroll
    for (int i2 = 0; i2 < 4; i2++)
#pragma unroll
        for (int j = 0; j < 4; j++) {
            float alo, ahi; UPK2(alo, ahi, acc2[i2][j]);
            atomicAdd(&g_acc[kb + ck0 + 2 * i2 + 0][dq + j], alo);
            atomicAdd(&g_acc[kb + ck0 + 2 * i2 + 1][dq + j], ahi);
        }
#pragma unroll
    for (int i = 0; i < 8; i++) {
        float v = (float)cnti[i];
#pragma unroll
        for (int off = 8; off > 0; off >>= 1)
            v += __shfl_down_sync(0xffffffffu, v, off, 16);
        if (tx == 0) atomicAdd(&g_cnt[kb + ck0 + i], v);
    }
}

// ------------------------------------------- final masked argmin
// Unflagged tiles (no c9-candidates): mask provably all-true -> single GEMM.
// Flagged tiles: dual GEMM with exact mask recompute (original path).

__global__ void __launch_bounds__(256) final_kernel(const float* __restrict__ x) {
    extern __shared__ float smem[];
    float* C9   = smem;
    float* C10  = C9 + 64 * 64;
    float* c29  = C10 + 64 * 64;
    float* c210 = c29 + 64;
    float* Xt   = c210 + 64;
    float* x2s  = Xt + 64 * 68;

    const int tid = threadIdx.x;
    const int kb  = blockIdx.y * TK;

    {
        int ck = tid >> 2, q = tid & 3;
        const float4* r9  = (const float4*)(&g_c[1][kb + ck][0] + q * 16);
        const float4* r10 = (const float4*)(&g_c[0][kb + ck][0] + q * 16);
#pragma unroll
        for (int i = 0; i < 4; i++) {
            float4 a = r9[i], b = r10[i];
            int dd = q * 16 + i * 4;
            C9[(dd + 0) * TK + ck] = a.x; C9[(dd + 1) * TK + ck] = a.y;
            C9[(dd + 2) * TK + ck] = a.z; C9[(dd + 3) * TK + ck] = a.w;
            C10[(dd + 0) * TK + ck] = b.x; C10[(dd + 1) * TK + ck] = b.y;
            C10[(dd + 2) * TK + ck] = b.z; C10[(dd + 3) * TK + ck] = b.w;
        }
    }
    __syncthreads();
    if (tid < TK) {
        float s9 = 0.f, s10 = 0.f;
#pragma unroll
        for (int d = 0; d < DIM; d++) {
            float a = C9[d * TK + tid];  s9  = fmaf(a, a, s9);
            float b = C10[d * TK + tid]; s10 = fmaf(b, b, s10);
        }
        c29[tid] = s9; c210[tid] = s10;
    }

    const int ty = tid >> 4, tx = tid & 15;
    const int ck0 = ty * 4, p0 = tx * 4;
    unsigned long long best[4] = {~0ull, ~0ull, ~0ull, ~0ull};

    for (int t = blockIdx.x; t < NT64; t += GXF) {
        const int tb = t * TN;
        __syncthreads();
        {
            int p = tid >> 2, q = tid & 3;
            const float4* row = (const float4*)(x + (size_t)(tb + p) * DIM + q * 16);
#pragma unroll
            for (int i = 0; i < 4; i++) {
                float4 v = row[i];
                int dd = q * 16 + i * 4;
                Xt[(dd + 0) * 68 + p] = v.x;
                Xt[(dd + 1) * 68 + p] = v.y;
                Xt[(dd + 2) * 68 + p] = v.z;
                Xt[(dd + 3) * 68 + p] = v.w;
            }
            if (tid < TN) x2s[tid] = g_x2[tb + tid];
        }
        __syncthreads();

        const int fl = g_tileflag[t];
        if (fl) {
            float S9[4][4] = {}, S10[4][4] = {};
#pragma unroll 2
            for (int dd = 0; dd < DIM; dd++) {
                float4 c9v = *(const float4*)(C9 + dd * TK + ck0);
                float4 cav = *(const float4*)(C10 + dd * TK + ck0);
                float4 xv4 = *(const float4*)(Xt + dd * 68 + p0);
                float a9[4] = {c9v.x, c9v.y, c9v.z, c9v.w};
                float aa[4] = {cav.x, cav.y, cav.z, cav.w};
                float xv[4] = {xv4.x, xv4.y, xv4.z, xv4.w};
#pragma unroll
                for (int i = 0; i < 4; i++)
#pragma unroll
                    for (int j = 0; j < 4; j++) {
                        S9[i][j]  = fmaf(a9[i], xv[j], S9[i][j]);
                        S10[i][j] = fmaf(aa[i], xv[j], S10[i][j]);
                    }
            }
#pragma unroll
            for (int j = 0; j < 4; j++) {
                float xv2 = x2s[p0 + j];
                unsigned idx = (unsigned)(tb + p0 + j);
#pragma unroll
                for (int i = 0; i < 4; i++) {
                    float d2m = fmaf(-2.f, S9[i][j], c29[ck0 + i] + xv2);
                    if (d2m < BW2) {
                        float d2 = fmaf(-2.f, S10[i][j], c210[ck0 + i] + xv2);
                        d2 = fmaxf(d2, 0.f);
                        unsigned long long key =
                            ((unsigned long long)__float_as_uint(d2) << 32) | idx;
                        if (key < best[i]) best[i] = key;
                    }
                }
            }
        } else {
            float S10[4][4] = {};
#pragma unroll 4
            for (int dd = 0; dd < DIM; dd++) {
                float4 cav = *(const float4*)(C10 + dd * TK + ck0);
                float4 xv4 = *(const float4*)(Xt + dd * 68 + p0);
                float aa[4] = {cav.x, cav.y, cav.z, cav.w};
                float xv[4] = {xv4.x, xv4.y, xv4.z, xv4.w};
#pragma unroll
                for (int i = 0; i < 4; i++)
#pragma unroll
                    for (int j = 0; j < 4; j++)
                        S10[i][j] = fmaf(aa[i], xv[j], S10[i][j]);
            }
#pragma unroll
            for (int j = 0; j < 4; j++) {
                float xv2 = x2s[p0 + j];
                unsigned idx = (unsigned)(tb + p0 + j);
#pragma unroll
                for (int i = 0; i < 4; i++) {
                    float d2 = fmaf(-2.f, S10[i][j], c210[ck0 + i] + xv2);
                    d2 = fmaxf(d2, 0.f);
                    unsigned long long key =
                        ((unsigned long long)__float_as_uint(d2) << 32) | idx;
                    if (key < best[i]) best[i] = key;
                }
            }
        }
    }

#pragma unroll
    for (int i = 0; i < 4; i++) {
        unsigned long long v = best[i];
#pragma unroll
        for (int off = 8; off > 0; off >>= 1) {
            unsigned long long o = __shfl_down_sync(0xffffffffu, v, off, 16);
            if (o < v) v = o;
        }
        if (tx == 0) atomicMin(&g_best[kb + ck0 + i], v);
    }
}

// ---------------------------------------------------------------- epilogue

__global__ void zero_out(float* out, int n) {
    int i = blockIdx.x * blockDim.x + threadIdx.x;
    if (i < n) out[i] = 0.f;
}

__global__ void finish_kernel(float* __restrict__ out, const float* __restrict__ x,
                              int out_size) {
    int k = blockIdx.x, d = threadIdx.x;
    if (out_size >= KC * DIM)
        out[k * DIM + d] = g_c[0][k][d];
    unsigned long long b = g_best[k];
    unsigned idx = (b == ~0ull) ? 0u : (unsigned)(b & 0xffffffffu);
    if (out_size >= 2 * KC * DIM)
        out[KC * DIM + k * DIM + d] = x[(size_t)idx * DIM + d];
    if (d == 0 && out_size >= 2 * KC * DIM + KC)
        out[2 * KC * DIM + k] = (float)idx;
}

// ---------------------------------------------------------------- launcher

extern "C" void kernel_launch(void* const* d_in, const int* in_sizes, int n_in,
                              void* d_out, int out_size) {
    const float* x = (const float*)d_in[0];
    const void* seed = d_in[1];
    float* out = (float*)d_out;
    (void)in_sizes; (void)n_in;

    const size_t iterSmem = (size_t)(64 * KB + KB + 64 * XTS + PB * XRS + PB * MSS + PB + 16)
                            * sizeof(float);
    const size_t finalSmem = (size_t)(2 * 64 * 64 + 2 * 64 + 64 * 68 + 64) * sizeof(float);
    cudaFuncSetAttribute(iter_kernel,  cudaFuncAttributeMaxDynamicSharedMemorySize, (int)iterSmem);
    cudaFuncSetAttribute(final_kernel, cudaFuncAttributeMaxDynamicSharedMemorySize, (int)finalSmem);

    x2_kernel<<<(NPTS + 255) / 256, 256>>>(x);
    detect_kernel<<<1, 128>>>(seed);
    seed_kernel<<<KC, DIM>>>(x, seed);
    zero_sum_kernel<<<1, 64>>>();
    sum_kernel<<<128, 256>>>(x);

    // iteration 1: dense (centers are data points, everything is a candidate)
    iter_kernel<<<dim3(GXI, KC / KB), 256, iterSmem>>>(x, 0);
    update_kernel<<<KC, DIM>>>(0);

    // iterations 2..10: conservative candidate filter + exact sparse check
    for (int it = 1; it < ITERS; it++) {
        cmax_kernel<<<1, KC>>>(it & 1);
        sparse_iter<<<148, 256>>>(x, it, (it == ITERS - 1) ? 1 : 0);
        update_kernel<<<KC, DIM>>>(it);
    }

    final_kernel<<<dim3(GXF, KC / TK), 256, finalSmem>>>(x);

    if (out_size > 0)
        zero_out<<<(out_size + 255) / 256, 256>>>(out, out_size);
    finish_kernel<<<KC, DIM>>>(out, x, out_size);
}